// round 1
// baseline (speedup 1.0000x reference)
#include <cuda_runtime.h>
#include <math.h>
#include <stdint.h>

#define B_    64
#define S_    512
#define H_    1024
#define HD2   512
#define L_    9
#define NTOK  (B_*S_)
#define EPS_  1e-5f

// ---------------- scratch (no allocation allowed; device globals) ----------
__device__ float g_mu[NTOK];
__device__ float g_rstd[NTOK];
__device__ float g_h[(size_t)NTOK * HD2];     // 64 MB fp32 intermediate (post-GELU)
__device__ float g_em[(size_t)NTOK * L_];     // emissions
__device__ float g_llh[B_];

// ---------------------------------------------------------------------------
// Kernel 1: per-row LayerNorm statistics (mean, rstd)
// ---------------------------------------------------------------------------
__global__ void ln_stats_kernel(const float* __restrict__ hs) {
    int row = blockIdx.x;
    const float4* p = (const float4*)(hs + (size_t)row * H_);
    float4 v = p[threadIdx.x];                       // 256 threads x float4 = 1024
    float s  = v.x + v.y + v.z + v.w;
    float ss = v.x*v.x + v.y*v.y + v.z*v.z + v.w*v.w;
    #pragma unroll
    for (int off = 16; off; off >>= 1) {
        s  += __shfl_down_sync(0xffffffffu, s,  off);
        ss += __shfl_down_sync(0xffffffffu, ss, off);
    }
    __shared__ float rs[8], rss[8];
    int w = threadIdx.x >> 5, ln = threadIdx.x & 31;
    if (ln == 0) { rs[w] = s; rss[w] = ss; }
    __syncthreads();
    if (threadIdx.x == 0) {
        float S = 0.f, SS = 0.f;
        #pragma unroll
        for (int i = 0; i < 8; i++) { S += rs[i]; SS += rss[i]; }
        float mu  = S * (1.0f / H_);
        float var = SS * (1.0f / H_) - mu * mu;
        g_mu[row]   = mu;
        g_rstd[row] = rsqrtf(var + EPS_);
    }
}

// ---------------------------------------------------------------------------
// Kernel 2: fused LN-normalize -> GEMM1 (M=32768,N=512,K=1024) -> +b1 -> GELU
// Classic 128x128x16 tile, 256 threads, 8x8 microtile, double-buffered smem.
// ---------------------------------------------------------------------------
#define BM 128
#define BN 128
#define BK 16
#define TM 8
#define TN 8

__global__ void __launch_bounds__(256, 1) gemm1_gelu_kernel(
    const float* __restrict__ A,      // hidden_states [NTOK][H_]
    const float* __restrict__ gamma,
    const float* __restrict__ beta,
    const float* __restrict__ W1,     // [H_][HD2]
    const float* __restrict__ b1)
{
    __shared__ float As[2][BK][BM + 4];
    __shared__ float Bs[2][BK][BN];

    const int tid = threadIdx.x;
    const int m0  = blockIdx.y * BM;
    const int n0  = blockIdx.x * BN;

    const int ar = tid >> 2;            // 0..63  (A row within tile, +64 on pass 2)
    const int ac = (tid & 3) << 2;      // 0,4,8,12 (A col within k-tile)
    const int br = tid >> 5;            // 0..7   (B row within k-tile, +8 on pass 2)
    const int bc = (tid & 31) << 2;     // B col
    const int tx = tid & 15, ty = tid >> 4;

    const float mu0 = g_mu[m0 + ar],      rs0 = g_rstd[m0 + ar];
    const float mu1 = g_mu[m0 + ar + 64], rs1 = g_rstd[m0 + ar + 64];

    float acc[TM][TN];
    #pragma unroll
    for (int i = 0; i < TM; i++)
        #pragma unroll
        for (int j = 0; j < TN; j++) acc[i][j] = 0.f;

    // prologue: tile 0
    {
        float4 a0 = *(const float4*)(A + (size_t)(m0 + ar)      * H_ + ac);
        float4 a1 = *(const float4*)(A + (size_t)(m0 + ar + 64) * H_ + ac);
        float4 g4 = *(const float4*)(gamma + ac);
        float4 be = *(const float4*)(beta  + ac);
        As[0][ac+0][ar]    = (a0.x - mu0) * rs0 * g4.x + be.x;
        As[0][ac+1][ar]    = (a0.y - mu0) * rs0 * g4.y + be.y;
        As[0][ac+2][ar]    = (a0.z - mu0) * rs0 * g4.z + be.z;
        As[0][ac+3][ar]    = (a0.w - mu0) * rs0 * g4.w + be.w;
        As[0][ac+0][ar+64] = (a1.x - mu1) * rs1 * g4.x + be.x;
        As[0][ac+1][ar+64] = (a1.y - mu1) * rs1 * g4.y + be.y;
        As[0][ac+2][ar+64] = (a1.z - mu1) * rs1 * g4.z + be.z;
        As[0][ac+3][ar+64] = (a1.w - mu1) * rs1 * g4.w + be.w;
        float4 w0 = *(const float4*)(W1 + (size_t)br      * HD2 + n0 + bc);
        float4 w1 = *(const float4*)(W1 + (size_t)(br + 8)* HD2 + n0 + bc);
        *(float4*)&Bs[0][br][bc]     = w0;
        *(float4*)&Bs[0][br + 8][bc] = w1;
    }
    __syncthreads();

    const int NK = H_ / BK;   // 64
    for (int t = 0; t < NK; ++t) {
        const int cur = t & 1;
        float4 a0, a1, g4, be, w0, w1;
        if (t + 1 < NK) {
            const int k = (t + 1) * BK;
            a0 = *(const float4*)(A + (size_t)(m0 + ar)      * H_ + k + ac);
            a1 = *(const float4*)(A + (size_t)(m0 + ar + 64) * H_ + k + ac);
            g4 = *(const float4*)(gamma + k + ac);
            be = *(const float4*)(beta  + k + ac);
            w0 = *(const float4*)(W1 + (size_t)(k + br)     * HD2 + n0 + bc);
            w1 = *(const float4*)(W1 + (size_t)(k + br + 8) * HD2 + n0 + bc);
        }
        #pragma unroll
        for (int kk = 0; kk < BK; ++kk) {
            float a[TM], b[TN];
            #pragma unroll
            for (int i = 0; i < TM; i++) a[i] = As[cur][kk][ty * TM + i];
            #pragma unroll
            for (int j = 0; j < TN; j++) b[j] = Bs[cur][kk][tx * TN + j];
            #pragma unroll
            for (int i = 0; i < TM; i++)
                #pragma unroll
                for (int j = 0; j < TN; j++)
                    acc[i][j] = fmaf(a[i], b[j], acc[i][j]);
        }
        if (t + 1 < NK) {
            const int nb = cur ^ 1;
            As[nb][ac+0][ar]    = (a0.x - mu0) * rs0 * g4.x + be.x;
            As[nb][ac+1][ar]    = (a0.y - mu0) * rs0 * g4.y + be.y;
            As[nb][ac+2][ar]    = (a0.z - mu0) * rs0 * g4.z + be.z;
            As[nb][ac+3][ar]    = (a0.w - mu0) * rs0 * g4.w + be.w;
            As[nb][ac+0][ar+64] = (a1.x - mu1) * rs1 * g4.x + be.x;
            As[nb][ac+1][ar+64] = (a1.y - mu1) * rs1 * g4.y + be.y;
            As[nb][ac+2][ar+64] = (a1.z - mu1) * rs1 * g4.z + be.z;
            As[nb][ac+3][ar+64] = (a1.w - mu1) * rs1 * g4.w + be.w;
            *(float4*)&Bs[nb][br][bc]     = w0;
            *(float4*)&Bs[nb][br + 8][bc] = w1;
        }
        __syncthreads();
    }

    // epilogue: + b1, exact GELU, store h
    float bias[TN];
    #pragma unroll
    for (int j = 0; j < TN; j++) bias[j] = b1[n0 + tx * TN + j];

    #pragma unroll
    for (int i = 0; i < TM; i++) {
        const int m = m0 + ty * TM + i;
        float r[TN];
        #pragma unroll
        for (int j = 0; j < TN; j++) {
            float c = acc[i][j] + bias[j];
            r[j] = 0.5f * c * (1.0f + erff(c * 0.70710678118654752f));
        }
        float* hp = g_h + (size_t)m * HD2 + n0 + tx * TN;
        *(float4*)(hp + 0) = make_float4(r[0], r[1], r[2], r[3]);
        *(float4*)(hp + 4) = make_float4(r[4], r[5], r[6], r[7]);
    }
}

// ---------------------------------------------------------------------------
// Kernel 3: GEMM2 h[NTOK,512] @ W2[512,9] + b2 -> emissions. Warp per token.
// ---------------------------------------------------------------------------
__global__ void __launch_bounds__(256) gemm2_kernel(
    const float* __restrict__ W2, const float* __restrict__ b2)
{
    __shared__ float w2s[HD2 * L_];   // 18 KB
    __shared__ float b2s[L_];
    for (int i = threadIdx.x; i < HD2 * L_; i += 256) w2s[i] = W2[i];
    if (threadIdx.x < L_) b2s[threadIdx.x] = b2[threadIdx.x];
    __syncthreads();

    const int warp = threadIdx.x >> 5;
    const int lane = threadIdx.x & 31;
    const int tok  = blockIdx.x * 8 + warp;

    const float4* hp = (const float4*)(g_h + (size_t)tok * HD2);
    float acc[L_];
    #pragma unroll
    for (int l = 0; l < L_; l++) acc[l] = 0.f;

    #pragma unroll
    for (int it = 0; it < 4; ++it) {               // 4 * 32 lanes * 4 = 512
        const int kq = it * 32 + lane;
        float4 v = hp[kq];
        const float* w = &w2s[(kq * 4) * L_];
        #pragma unroll
        for (int l = 0; l < L_; l++)
            acc[l] += v.x * w[l] + v.y * w[L_ + l] + v.z * w[2*L_ + l] + v.w * w[3*L_ + l];
    }
    #pragma unroll
    for (int l = 0; l < L_; l++)
        #pragma unroll
        for (int off = 16; off; off >>= 1)
            acc[l] += __shfl_down_sync(0xffffffffu, acc[l], off);
    if (lane == 0) {
        float* out = g_em + (size_t)tok * L_;
        #pragma unroll
        for (int l = 0; l < L_; l++) out[l] = acc[l] + b2s[l];
    }
}

// ---------------------------------------------------------------------------
// Kernel 4: CRF numerator + forward algorithm. One warp per sequence.
// Lanes 0..8 carry the 9-state score; full-warp shfl for logsumexp.
// ---------------------------------------------------------------------------
__global__ void crf_kernel(const float* __restrict__ st,
                           const float* __restrict__ et,
                           const float* __restrict__ trans,
                           const int*   __restrict__ labels,
                           const int*   __restrict__ am)
{
    const int b    = blockIdx.x;
    const int lane = threadIdx.x;
    const float* em  = g_em + (size_t)b * S_ * L_;
    const int*   lab = labels + (size_t)b * S_;
    const int*   amk = am     + (size_t)b * S_;

    // ---- numerator (lane-parallel over t) ----
    float part = 0.f;
    int   cnt  = 0;
    for (int t = lane; t < S_; t += 32) {
        int  l  = lab[t];
        bool rw = (l != -100) && (amk[t] == 1);     // raw mask rule
        bool mk = (t == 0) ? true : rw;             // position-0 override
        if (mk) cnt++;
        if (t > 0 && rw) {
            int tp = lab[t - 1]; if (tp == -100) tp = 0;
            int tc = l;          if (tc == -100) tc = 0;
            part += trans[tp * L_ + tc] + em[t * L_ + tc];
        }
    }
    #pragma unroll
    for (int off = 16; off; off >>= 1) {
        part += __shfl_down_sync(0xffffffffu, part, off);
        cnt  += __shfl_down_sync(0xffffffffu, cnt,  off);
    }
    float num = 0.f;
    if (lane == 0) {
        int tg0 = lab[0]; if (tg0 == -100) tg0 = 0;
        num = part + st[tg0] + em[tg0];
        int se = cnt - 1;                            // seq_ends = sum(mask)-1
        int lt = lab[se]; if (lt == -100) lt = 0;
        num += et[lt];
    }

    // ---- denominator: serial forward scan ----
    const int j = lane;
    float tr[L_];
    if (j < L_) {
        #pragma unroll
        for (int i = 0; i < L_; i++) tr[i] = trans[i * L_ + j];
    }
    float score = (j < L_) ? (st[j] + em[j]) : -1e30f;

    for (int t = 1; t < S_; ++t) {
        int  l  = lab[t];
        bool mk = (l != -100) && (amk[t] == 1);      // warp-uniform
        float emt = (j < L_) ? em[t * L_ + j] : 0.f;
        float v[L_];
        float mx = -1e30f;
        #pragma unroll
        for (int i = 0; i < L_; i++) {
            v[i] = __shfl_sync(0xffffffffu, score, i) + tr[i];
            mx = fmaxf(mx, v[i]);
        }
        float s = 0.f;
        #pragma unroll
        for (int i = 0; i < L_; i++) s += __expf(v[i] - mx);
        float nxt = mx + __logf(s) + emt;
        score = mk ? nxt : score;
    }

    float fv = (j < L_) ? (score + et[j]) : -1e30f;
    float mx = fv;
    #pragma unroll
    for (int off = 16; off; off >>= 1) mx = fmaxf(mx, __shfl_xor_sync(0xffffffffu, mx, off));
    float s = (j < L_) ? __expf(fv - mx) : 0.f;
    #pragma unroll
    for (int off = 16; off; off >>= 1) s += __shfl_xor_sync(0xffffffffu, s, off);
    float denom = mx + __logf(s);

    if (lane == 0) g_llh[b] = num - denom;
}

// ---------------------------------------------------------------------------
// Kernel 5: loss = -mean(llh)
// ---------------------------------------------------------------------------
__global__ void finalize_kernel(float* __restrict__ out) {
    int t = threadIdx.x;                     // 64 threads
    float v = g_llh[t];
    #pragma unroll
    for (int off = 16; off; off >>= 1) v += __shfl_down_sync(0xffffffffu, v, off);
    __shared__ float r[2];
    if ((t & 31) == 0) r[t >> 5] = v;
    __syncthreads();
    if (t == 0) out[0] = -((r[0] + r[1]) * (1.0f / B_));
}

// ---------------------------------------------------------------------------
extern "C" void kernel_launch(void* const* d_in, const int* in_sizes, int n_in,
                              void* d_out, int out_size)
{
    const float* hs    = (const float*)d_in[0];
    const float* gamma = (const float*)d_in[1];
    const float* beta  = (const float*)d_in[2];
    const float* W1    = (const float*)d_in[3];
    const float* b1    = (const float*)d_in[4];
    const float* W2    = (const float*)d_in[5];
    const float* b2    = (const float*)d_in[6];
    const float* st    = (const float*)d_in[7];
    const float* et    = (const float*)d_in[8];
    const float* trans = (const float*)d_in[9];
    const int*   labels= (const int*)d_in[10];
    const int*   am    = (const int*)d_in[11];

    ln_stats_kernel<<<NTOK, 256>>>(hs);

    dim3 g1(HD2 / BN, NTOK / BM);            // (4, 256)
    gemm1_gelu_kernel<<<g1, 256>>>(hs, gamma, beta, W1, b1);

    gemm2_kernel<<<NTOK / 8, 256>>>(W2, b2);

    crf_kernel<<<B_, 32>>>(st, et, trans, labels, am);

    finalize_kernel<<<1, 64>>>((float*)d_out);
}

// round 2
// speedup vs baseline: 3.0802x; 3.0802x over previous
#include <cuda_runtime.h>
#include <cuda_bf16.h>
#include <math.h>
#include <stdint.h>

#define B_    64
#define S_    512
#define H_    1024
#define HD2   512
#define L_    9
#define NTOK  (B_*S_)
#define EPS_  1e-5f
#define LOG2E_ 1.4426950408889634f
#define LN2_   0.6931471805599453f

// ---------------- device scratch (no allocation allowed) -------------------
__device__ __nv_bfloat16 g_xb[(size_t)NTOK * H_];    // 64 MB: LN-normalized X, bf16
__device__ __nv_bfloat16 g_w1t[(size_t)HD2 * H_];    // 1 MB:  W1^T bf16 [N][K]
__device__ __nv_bfloat16 g_hb[(size_t)NTOK * HD2];   // 32 MB: post-GELU h, bf16
__device__ float g_em[(size_t)NTOK * L_];            // emissions fp32
__device__ float g_llh[B_];

// ---------------------------------------------------------------------------
__device__ __forceinline__ float ex2f_(float x){ float y; asm("ex2.approx.ftz.f32 %0,%1;":"=f"(y):"f"(x)); return y; }
__device__ __forceinline__ float lg2f_(float x){ float y; asm("lg2.approx.ftz.f32 %0,%1;":"=f"(y):"f"(x)); return y; }

__device__ __forceinline__ void cp16(void* sm, const void* g){
    uint32_t a = (uint32_t)__cvta_generic_to_shared(sm);
    asm volatile("cp.async.cg.shared.global [%0], [%1], 16;" :: "r"(a), "l"(g));
}

// ---------------------------------------------------------------------------
// Kernel 1: LayerNorm -> normalized bf16 X
// ---------------------------------------------------------------------------
__global__ void ln_norm_kernel(const float* __restrict__ hs,
                               const float* __restrict__ gamma,
                               const float* __restrict__ beta)
{
    const int row = blockIdx.x;
    const int tid = threadIdx.x;                      // 256
    float4 v = ((const float4*)(hs + (size_t)row * H_))[tid];
    float s  = v.x + v.y + v.z + v.w;
    float ss = v.x*v.x + v.y*v.y + v.z*v.z + v.w*v.w;
    #pragma unroll
    for (int off = 16; off; off >>= 1) {
        s  += __shfl_down_sync(0xffffffffu, s,  off);
        ss += __shfl_down_sync(0xffffffffu, ss, off);
    }
    __shared__ float rs_[8], rss_[8];
    __shared__ float s_mu, s_rs;
    if ((tid & 31) == 0) { rs_[tid >> 5] = s; rss_[tid >> 5] = ss; }
    __syncthreads();
    if (tid == 0) {
        float S = 0.f, SS = 0.f;
        #pragma unroll
        for (int i = 0; i < 8; i++) { S += rs_[i]; SS += rss_[i]; }
        float mu  = S * (1.0f / H_);
        float var = SS * (1.0f / H_) - mu * mu;
        s_mu = mu; s_rs = rsqrtf(var + EPS_);
    }
    __syncthreads();
    const float mu = s_mu, rstd = s_rs;
    float4 g4 = ((const float4*)gamma)[tid];
    float4 b4 = ((const float4*)beta)[tid];
    float o0 = (v.x - mu) * rstd * g4.x + b4.x;
    float o1 = (v.y - mu) * rstd * g4.y + b4.y;
    float o2 = (v.z - mu) * rstd * g4.z + b4.z;
    float o3 = (v.w - mu) * rstd * g4.w + b4.w;
    __nv_bfloat162 p0 = __floats2bfloat162_rn(o0, o1);
    __nv_bfloat162 p1 = __floats2bfloat162_rn(o2, o3);
    uint2 pk = make_uint2(*(uint32_t*)&p0, *(uint32_t*)&p1);
    *(uint2*)(g_xb + (size_t)row * H_ + tid * 4) = pk;
}

// ---------------------------------------------------------------------------
// Kernel 2: W1 [K=1024][N=512] fp32 -> W1^T bf16 [N][K]
// ---------------------------------------------------------------------------
__global__ void w1_transpose_kernel(const float* __restrict__ W1)
{
    __shared__ float tile[32][33];
    const int n0 = blockIdx.x * 32, k0 = blockIdx.y * 32;
    const int tx = threadIdx.x, ty = threadIdx.y;   // (32, 8)
    #pragma unroll
    for (int i = 0; i < 4; i++)
        tile[ty + 8*i][tx] = W1[(size_t)(k0 + ty + 8*i) * HD2 + n0 + tx];
    __syncthreads();
    #pragma unroll
    for (int i = 0; i < 4; i++)
        g_w1t[(size_t)(n0 + ty + 8*i) * H_ + k0 + tx] =
            __float2bfloat16(tile[tx][ty + 8*i]);
}

// ---------------------------------------------------------------------------
// Kernel 3: GEMM1 bf16 tensor-core: h = GELU(Xn @ W1 + b1)
// 128x128x32 block tile, 256 thr (8 warps: 4(M)x2(N)), mma.m16n8k16 bf16
// ---------------------------------------------------------------------------
#define KPAD 40   // 32 + 8 halves padding -> conflict-free fragment LDS

__global__ void __launch_bounds__(256, 2) gemm1_tc_kernel(const float* __restrict__ b1)
{
    __shared__ __align__(16) __nv_bfloat16 As[2][128 * KPAD];
    __shared__ __align__(16) __nv_bfloat16 Bs[2][128 * KPAD];

    const int tid  = threadIdx.x;
    const int m0   = blockIdx.y * 128;
    const int n0   = blockIdx.x * 128;
    const int warp = tid >> 5, lane = tid & 31;
    const int wm   = warp & 3;        // 0..3 (32-row M subtile)
    const int wn   = warp >> 2;       // 0..1 (64-col N subtile)
    const int r    = lane >> 2, tig = lane & 3;

    // loader mapping: thread -> (row 0..127, two 16B chunks)
    const int lrow = tid >> 1;
    const int lcc  = (tid & 1) * 2;   // chunks {0,1} or {2,3} of the 64B row
    const __nv_bfloat16* Ag = g_xb  + (size_t)(m0 + lrow) * H_;
    const __nv_bfloat16* Bg = g_w1t + (size_t)(n0 + lrow) * H_;

    float acc[2][8][4];
    #pragma unroll
    for (int mt = 0; mt < 2; mt++)
        #pragma unroll
        for (int nt = 0; nt < 8; nt++)
            #pragma unroll
            for (int e = 0; e < 4; e++) acc[mt][nt][e] = 0.f;

    // prologue: tile 0
    cp16(&As[0][lrow * KPAD + lcc * 8],       Ag + lcc * 8);
    cp16(&As[0][lrow * KPAD + (lcc + 1) * 8], Ag + (lcc + 1) * 8);
    cp16(&Bs[0][lrow * KPAD + lcc * 8],       Bg + lcc * 8);
    cp16(&Bs[0][lrow * KPAD + (lcc + 1) * 8], Bg + (lcc + 1) * 8);
    asm volatile("cp.async.commit_group;");

    const int NT = H_ / 32;   // 32 k-tiles
    for (int t = 0; t < NT; ++t) {
        const int buf = t & 1;
        if (t + 1 < NT) {
            const int k0 = (t + 1) * 32;
            cp16(&As[buf ^ 1][lrow * KPAD + lcc * 8],       Ag + k0 + lcc * 8);
            cp16(&As[buf ^ 1][lrow * KPAD + (lcc + 1) * 8], Ag + k0 + (lcc + 1) * 8);
            cp16(&Bs[buf ^ 1][lrow * KPAD + lcc * 8],       Bg + k0 + lcc * 8);
            cp16(&Bs[buf ^ 1][lrow * KPAD + (lcc + 1) * 8], Bg + k0 + (lcc + 1) * 8);
            asm volatile("cp.async.commit_group;");
            asm volatile("cp.async.wait_group 1;");
        } else {
            asm volatile("cp.async.wait_group 0;");
        }
        __syncthreads();

        const uint32_t* As32 = (const uint32_t*)As[buf];
        const uint32_t* Bs32 = (const uint32_t*)Bs[buf];
        #pragma unroll
        for (int kt = 0; kt < 2; kt++) {
            const int kw = kt * 8;             // 16 halves = 8 words
            uint32_t a[2][4];
            #pragma unroll
            for (int mt = 0; mt < 2; mt++) {
                const int mrow = wm * 32 + mt * 16 + r;
                a[mt][0] = As32[ mrow      * (KPAD/2) + kw + tig];
                a[mt][1] = As32[(mrow + 8) * (KPAD/2) + kw + tig];
                a[mt][2] = As32[ mrow      * (KPAD/2) + kw + tig + 4];
                a[mt][3] = As32[(mrow + 8) * (KPAD/2) + kw + tig + 4];
            }
            uint32_t b[8][2];
            #pragma unroll
            for (int nt = 0; nt < 8; nt++) {
                const int nrow = wn * 64 + nt * 8 + r;
                b[nt][0] = Bs32[nrow * (KPAD/2) + kw + tig];
                b[nt][1] = Bs32[nrow * (KPAD/2) + kw + tig + 4];
            }
            #pragma unroll
            for (int mt = 0; mt < 2; mt++)
                #pragma unroll
                for (int nt = 0; nt < 8; nt++)
                    asm volatile(
                        "mma.sync.aligned.m16n8k16.row.col.f32.bf16.bf16.f32 "
                        "{%0,%1,%2,%3},{%4,%5,%6,%7},{%8,%9},{%0,%1,%2,%3};"
                        : "+f"(acc[mt][nt][0]), "+f"(acc[mt][nt][1]),
                          "+f"(acc[mt][nt][2]), "+f"(acc[mt][nt][3])
                        : "r"(a[mt][0]), "r"(a[mt][1]), "r"(a[mt][2]), "r"(a[mt][3]),
                          "r"(b[nt][0]), "r"(b[nt][1]));
        }
        __syncthreads();
    }

    // epilogue: +b1, exact GELU, bf16 store
    #pragma unroll
    for (int mt = 0; mt < 2; mt++) {
        const int row = m0 + wm * 32 + mt * 16 + r;
        #pragma unroll
        for (int nt = 0; nt < 8; nt++) {
            const int col = n0 + wn * 64 + nt * 8 + 2 * tig;
            float2 bb = *(const float2*)(b1 + col);
            float c0 = acc[mt][nt][0] + bb.x;
            float c1 = acc[mt][nt][1] + bb.y;
            float c2 = acc[mt][nt][2] + bb.x;
            float c3 = acc[mt][nt][3] + bb.y;
            c0 = 0.5f * c0 * (1.0f + erff(c0 * 0.70710678118654752f));
            c1 = 0.5f * c1 * (1.0f + erff(c1 * 0.70710678118654752f));
            c2 = 0.5f * c2 * (1.0f + erff(c2 * 0.70710678118654752f));
            c3 = 0.5f * c3 * (1.0f + erff(c3 * 0.70710678118654752f));
            *(__nv_bfloat162*)(g_hb + (size_t)row * HD2 + col)       = __floats2bfloat162_rn(c0, c1);
            *(__nv_bfloat162*)(g_hb + (size_t)(row + 8) * HD2 + col) = __floats2bfloat162_rn(c2, c3);
        }
    }
}

// ---------------------------------------------------------------------------
// Kernel 4: GEMM2 h[NTOK,512](bf16) @ W2[512,9] + b2 -> emissions (warp/token)
// ---------------------------------------------------------------------------
__global__ void __launch_bounds__(256) gemm2_kernel(
    const float* __restrict__ W2, const float* __restrict__ b2)
{
    __shared__ float w2s[HD2 * L_];   // 18 KB [k][l]
    __shared__ float b2s[L_];
    for (int i = threadIdx.x; i < HD2 * L_; i += 256) w2s[i] = W2[i];
    if (threadIdx.x < L_) b2s[threadIdx.x] = b2[threadIdx.x];
    __syncthreads();

    const int warp = threadIdx.x >> 5;
    const int lane = threadIdx.x & 31;
    const int tok  = blockIdx.x * 8 + warp;

    const uint32_t* hp = (const uint32_t*)(g_hb + (size_t)tok * HD2);
    float acc[L_];
    #pragma unroll
    for (int l = 0; l < L_; l++) acc[l] = 0.f;

    #pragma unroll
    for (int e = 0; e < 8; ++e) {                 // 8 * 32 lanes * 2 halves = 512
        const int kp = lane + 32 * e;             // bf16 pair index
        uint32_t h2 = hp[kp];
        float h0 = __uint_as_float(h2 << 16);
        float h1 = __uint_as_float(h2 & 0xffff0000u);
        const float* w = &w2s[(2 * kp) * L_];
        #pragma unroll
        for (int l = 0; l < L_; l++)
            acc[l] = fmaf(h0, w[l], fmaf(h1, w[L_ + l], acc[l]));
    }
    #pragma unroll
    for (int l = 0; l < L_; l++)
        #pragma unroll
        for (int off = 16; off; off >>= 1)
            acc[l] += __shfl_down_sync(0xffffffffu, acc[l], off);
    if (lane == 0) {
        float* out = g_em + (size_t)tok * L_;
        #pragma unroll
        for (int l = 0; l < L_; l++) out[l] = acc[l] + b2s[l];
    }
}

// ---------------------------------------------------------------------------
// Kernel 5: CRF. Numerator lane-parallel; forward scan in base-2 with
// exp-shuffle trick (1 EX2 + 9 SHFL + 9 FFMA + 1 LG2 per step).
// ---------------------------------------------------------------------------
__global__ void crf_kernel(const float* __restrict__ st,
                           const float* __restrict__ et,
                           const float* __restrict__ trans,
                           const int*   __restrict__ labels,
                           const int*   __restrict__ am)
{
    const int b    = blockIdx.x;
    const int lane = threadIdx.x;
    const float* em  = g_em + (size_t)b * S_ * L_;
    const int*   lab = labels + (size_t)b * S_;
    const int*   amk = am     + (size_t)b * S_;

    // ---- numerator ----
    float part = 0.f;
    int   cnt  = 0;
    for (int t = lane; t < S_; t += 32) {
        int  l  = lab[t];
        bool rw = (l != -100) && (amk[t] == 1);
        bool mk = (t == 0) ? true : rw;
        if (mk) cnt++;
        if (t > 0 && rw) {
            int tp = lab[t - 1]; if (tp == -100) tp = 0;
            int tc = l;          if (tc == -100) tc = 0;
            part += trans[tp * L_ + tc] + em[t * L_ + tc];
        }
    }
    #pragma unroll
    for (int off = 16; off; off >>= 1) {
        part += __shfl_down_sync(0xffffffffu, part, off);
        cnt  += __shfl_down_sync(0xffffffffu, cnt,  off);
    }
    float num = 0.f;
    if (lane == 0) {
        int tg0 = lab[0]; if (tg0 == -100) tg0 = 0;
        num = part + st[tg0] + em[tg0];
        int se = cnt - 1;
        int lt = lab[se]; if (lt == -100) lt = 0;
        num += et[lt];
    }

    // ---- denominator: base-2 forward scan ----
    const int j = lane;
    float c_[L_];                                   // e^{trans[i][j]}
    if (j < L_) {
        #pragma unroll
        for (int i = 0; i < L_; i++) c_[i] = ex2f_(trans[i * L_ + j] * LOG2E_);
    } else {
        #pragma unroll
        for (int i = 0; i < L_; i++) c_[i] = 0.f;
    }
    float S2 = (j < L_) ? (st[j] + em[j]) * LOG2E_ : -1e30f;
    float C2 = 0.f;

    for (int t = 1; t < S_; ++t) {
        if ((t & 15) == 0) {                        // periodic renorm
            float m = __shfl_sync(0xffffffffu, S2, 0);
            S2 -= m; C2 += m;
        }
        float p = ex2f_(S2);
        float pa[L_];
        #pragma unroll
        for (int i = 0; i < L_; i++) pa[i] = __shfl_sync(0xffffffffu, p, i);
        int  l  = lab[t];
        bool mk = (l != -100) && (amk[t] == 1);
        float emj = (j < L_) ? em[t * L_ + j] : 0.f;
        float s = pa[0] * c_[0];
        #pragma unroll
        for (int i = 1; i < L_; i++) s = fmaf(pa[i], c_[i], s);
        float nxt = lg2f_(s) + emj * LOG2E_;
        S2 = mk ? nxt : S2;
    }

    float fv = (j < L_) ? (S2 + et[j] * LOG2E_) : -1e30f;
    float pv = (j < L_) ? ex2f_(fv) : 0.f;
    #pragma unroll
    for (int off = 16; off; off >>= 1) pv += __shfl_xor_sync(0xffffffffu, pv, off);
    float denom = (C2 + lg2f_(pv)) * LN2_;

    if (lane == 0) g_llh[b] = num - denom;
}

// ---------------------------------------------------------------------------
// Kernel 6: loss = -mean(llh)
// ---------------------------------------------------------------------------
__global__ void finalize_kernel(float* __restrict__ out) {
    int t = threadIdx.x;                     // 64
    float v = g_llh[t];
    #pragma unroll
    for (int off = 16; off; off >>= 1) v += __shfl_down_sync(0xffffffffu, v, off);
    __shared__ float r[2];
    if ((t & 31) == 0) r[t >> 5] = v;
    __syncthreads();
    if (t == 0) out[0] = -((r[0] + r[1]) * (1.0f / B_));
}

// ---------------------------------------------------------------------------
extern "C" void kernel_launch(void* const* d_in, const int* in_sizes, int n_in,
                              void* d_out, int out_size)
{
    const float* hs    = (const float*)d_in[0];
    const float* gamma = (const float*)d_in[1];
    const float* beta  = (const float*)d_in[2];
    const float* W1    = (const float*)d_in[3];
    const float* b1    = (const float*)d_in[4];
    const float* W2    = (const float*)d_in[5];
    const float* b2    = (const float*)d_in[6];
    const float* st    = (const float*)d_in[7];
    const float* et    = (const float*)d_in[8];
    const float* trans = (const float*)d_in[9];
    const int*   labels= (const int*)d_in[10];
    const int*   am    = (const int*)d_in[11];

    ln_norm_kernel<<<NTOK, 256>>>(hs, gamma, beta);
    w1_transpose_kernel<<<dim3(HD2 / 32, H_ / 32), dim3(32, 8)>>>(W1);
    gemm1_tc_kernel<<<dim3(HD2 / 128, NTOK / 128), 256>>>(b1);
    gemm2_kernel<<<NTOK / 8, 256>>>(W2, b2);
    crf_kernel<<<B_, 32>>>(st, et, trans, labels, am);
    finalize_kernel<<<1, 64>>>((float*)d_out);
}